// round 10
// baseline (speedup 1.0000x reference)
#include <cuda_runtime.h>
#include <cstdint>

// weight_quantize_fn: out = alpha * SF * q_kept * sign, with group-of-16 term budget.
// R8: kernels are at their measured memory walls (read-only ~4.1 TB/s, R+W ~6.4 TB/s
//     effective). Attack the ~5-6us of inter-kernel overhead instead:
//     - reduceB+reduceC merged into one 1-CTA kernel
//     - PDL (programmatic stream serialization) on reduceBC and quant; quant issues
//       its input loads BEFORE griddepcontrol.wait to overlap launch + load latency.

#define AT 256                  // reduceA block
#define MAXP 65536              // max partials (CTAs of reduceA)
#define QT 256

__device__ float2 g_part[MAXP];      // per-CTA (sum, sumsq) fp32 partials
__device__ float  g_consts[4];       // [0]=1/(std*alpha), [1]=-mean/(std*alpha), [2]=SF*alpha

typedef unsigned long long u64;

// ---- PDL primitives ----
__device__ __forceinline__ void pdl_wait() {
    asm volatile("griddepcontrol.wait;" ::: "memory");
}
__device__ __forceinline__ void pdl_trigger() {
    asm volatile("griddepcontrol.launch_dependents;");
}

// ---- packed f32x2 helpers (Blackwell) ----
__device__ __forceinline__ u64 pk2(float lo, float hi) {
    u64 r; asm("mov.b64 %0, {%1, %2};" : "=l"(r) : "f"(lo), "f"(hi)); return r;
}
__device__ __forceinline__ void upk2(u64 v, float& lo, float& hi) {
    asm("mov.b64 {%0, %1}, %2;" : "=f"(lo), "=f"(hi) : "l"(v));
}
__device__ __forceinline__ u64 ffma2(u64 a, u64 b, u64 c) {
    u64 d; asm("fma.rn.f32x2 %0, %1, %2, %3;" : "=l"(d) : "l"(a), "l"(b), "l"(c)); return d;
}
__device__ __forceinline__ u64 fadd2(u64 a, u64 b) {
    u64 d; asm("add.rn.f32x2 %0, %1, %2;" : "=l"(d) : "l"(a), "l"(b)); return d;
}
__device__ __forceinline__ u64 fmul2(u64 a, u64 b) {
    u64 d; asm("mul.rn.f32x2 %0, %1, %2;" : "=l"(d) : "l"(a), "l"(b)); return d;
}
__device__ __forceinline__ void stcs4(float4* p, float4 v) {
    asm volatile("st.global.cs.v4.f32 [%0], {%1, %2, %3, %4};"
                 :: "l"(p), "f"(v.x), "f"(v.y), "f"(v.z), "f"(v.w) : "memory");
}

// ---- stage A: one-shot CTAs, 1 float4/thread, fp32 partial per CTA ----
__global__ void __launch_bounds__(AT) reduceA(const float4* __restrict__ x, int nvec) {
    int idx = blockIdx.x * AT + threadIdx.x;
    float s = 0.f, q = 0.f;
    if (idx < nvec) {
        float4 a = x[idx];
        s = (a.x + a.y) + (a.z + a.w);
        q = (a.x * a.x + a.y * a.y) + (a.z * a.z + a.w * a.w);
    }
#pragma unroll
    for (int o = 16; o > 0; o >>= 1) {
        s += __shfl_down_sync(0xffffffffu, s, o);
        q += __shfl_down_sync(0xffffffffu, q, o);
    }
    __shared__ float ssw[AT / 32], sqw[AT / 32];
    int wid = threadIdx.x >> 5, lane = threadIdx.x & 31;
    if (lane == 0) { ssw[wid] = s; sqw[wid] = q; }
    __syncthreads();
    if (threadIdx.x == 0) {
        float ts = 0.f, tq = 0.f;
#pragma unroll
        for (int i = 0; i < AT / 32; i++) { ts += ssw[i]; tq += sqw[i]; }
        g_part[blockIdx.x] = make_float2(ts, tq);
    }
    pdl_trigger();   // all CTAs signal; dependents get visibility of g_part
}

// ---- stage BC: single CTA folds partials -> mean/std -> constants ----
__global__ void __launch_bounds__(1024) reduceBC(const float* __restrict__ alpha_p,
                                                 int nparts, long long n) {
    __shared__ double ss[1024], sq[1024];
    pdl_wait();                              // g_part from reduceA must be visible
    double s = 0.0, q = 0.0;
    for (int i = threadIdx.x; i < nparts; i += 1024) {
        float2 p = g_part[i];
        s += (double)p.x;
        q += (double)p.y;
    }
    ss[threadIdx.x] = s; sq[threadIdx.x] = q;
    __syncthreads();
    for (int o = 512; o > 0; o >>= 1) {
        if (threadIdx.x < o) {
            ss[threadIdx.x] += ss[threadIdx.x + o];
            sq[threadIdx.x] += sq[threadIdx.x + o];
        }
        __syncthreads();
    }
    if (threadIdx.x == 0) {
        double N = (double)n;
        double mean = ss[0] / N;
        double var  = (sq[0] - N * mean * mean) / (N - 1.0);   // unbiased (ddof=1)
        double stdv = sqrt(var);
        double alpha = (double)(*alpha_p);
        double inv = 1.0 / (stdv * alpha);
        g_consts[0] = (float)inv;
        g_consts[1] = (float)(-mean * inv);
        g_consts[2] = (float)((double)(1.0f / 7.0f) * alpha);  // SF (fp32 1/7) * alpha
    }
    __syncthreads();
    pdl_trigger();   // after g_consts store: dependents see the constants
}

// ---- quantize: one float4 per thread; 4-lane clusters own one group of 16 ----
__global__ void __launch_bounds__(QT) quant(const float4* __restrict__ xv,
                                            float4* __restrict__ ov,
                                            const int* __restrict__ ntp, int nvec) {
    // Reverse block order: consume the L2-resident tail left by reduceA first.
    int rb = gridDim.x - 1 - blockIdx.x;
    int idx = rb * blockDim.x + threadIdx.x;
    if (idx >= nvec) { pdl_wait(); return; }

    // ---- pre-wait section: everything independent of the reduction ----
    float4 v = xv[idx];                           // input load in flight during primary tail
    int nts = __ldg(ntp);
    pdl_wait();                                   // now g_consts is visible

    float scale = g_consts[0], bias = g_consts[1], C = g_consts[2];
    const float MAGIC = 8388608.0f;               // 2^23: RN add == round-half-even to int
    u64 s2 = pk2(scale, scale);
    u64 b2 = pk2(bias, bias);
    u64 seven2  = pk2(7.0f, 7.0f);
    u64 magic2  = pk2(MAGIC, MAGIC);
    u64 nmagic2 = pk2(-MAGIC, -MAGIC);
    u64 C2 = pk2(C, C);

    float X[4] = {v.x, v.y, v.z, v.w};

    float t[4], f[4];
#pragma unroll
    for (int p = 0; p < 2; p++) {
        u64 t2 = ffma2(pk2(X[2 * p], X[2 * p + 1]), s2, b2);    // t = x*scale + bias
        upk2(t2, t[2 * p], t[2 * p + 1]);
        float al = fminf(fabsf(t[2 * p]), 1.0f);                // |clip(t)| — FMNMX with |src|
        float ah = fminf(fabsf(t[2 * p + 1]), 1.0f);
        u64 f2 = ffma2(pk2(al, ah), seven2, magic2);            // f = 2^23 + q (round-half-even)
        upk2(f2, f[2 * p], f[2 * p + 1]);
    }

    // Group sum of q over the 16 elements owned by this 4-lane cluster.
    int qs = __float_as_int(f[0]) + __float_as_int(f[1]) +
             __float_as_int(f[2]) + __float_as_int(f[3]);
    qs += __shfl_xor_sync(0xffffffffu, qs, 1);
    qs += __shfl_xor_sync(0xffffffffu, qs, 2);

    int budget = nts * 16;                        // num_terms * group_size

    float4 w;
    float* r = &w.x;
    // popc(q) <= (q+1)/2 for q in [0,7]  =>  sum(q) <= 2*budget-16 guarantees terms <= budget.
    if ((qs & 0xff) <= 2 * budget - 16) {
        // Fast path: every term kept -> qk == q.
#pragma unroll
        for (int p = 0; p < 2; p++) {
            u64 qf2 = fadd2(pk2(f[2 * p], f[2 * p + 1]), nmagic2);  // exact: qf = q as float
            u64 o2  = fmul2(qf2, C2);                               // |out| = q*SF*alpha
            float ol, oh; upk2(o2, ol, oh);
            r[2 * p]     = __int_as_float(__float_as_int(ol) | (__float_as_int(t[2 * p])     & 0x80000000));
            r[2 * p + 1] = __int_as_float(__float_as_int(oh) | (__float_as_int(t[2 * p + 1]) & 0x80000000));
        }
    } else {
        // Exact path (rare): stable-descending-sort semantics.
        int lane = threadIdx.x & 31;
        unsigned cmask = 0xFu << (lane & ~3);     // the 4 lanes of this cluster
        int pos = (lane & 3) * 4;                 // this lane's element offset in the group
        int m1 = 0, m2 = 0, m4 = 0;
#pragma unroll
        for (int k = 0; k < 4; k++) {
            int q = __float_as_int(f[k]) & 7;
            m1 |= (q & 1) << (pos + k);
            m2 |= ((q >> 1) & 1) << (pos + k);
            m4 |= ((q >> 2) & 1) << (pos + k);
        }
        m1 |= __shfl_xor_sync(cmask, m1, 1);  m1 |= __shfl_xor_sync(cmask, m1, 2);
        m2 |= __shfl_xor_sync(cmask, m2, 1);  m2 |= __shfl_xor_sync(cmask, m2, 2);
        m4 |= __shfl_xor_sync(cmask, m4, 1);  m4 |= __shfl_xor_sync(cmask, m4, 2);
        int c4 = min(__popc(m4), budget);
        int rem = budget - c4;
        int c2 = min(__popc(m2), rem); rem -= c2;
        int c1 = min(__popc(m1), rem);
        if (c1 < 0) c1 = 0;
#pragma unroll
        for (int k = 0; k < 4; k++) {
            int i16 = pos + k;
            int below = (1 << i16) - 1;
            int k4 = ((m4 >> i16) & 1) & ((__popc(m4 & below) < c4) ? 1 : 0);
            int k2 = ((m2 >> i16) & 1) & ((__popc(m2 & below) < c2) ? 1 : 0);
            int k1 = ((m1 >> i16) & 1) & ((__popc(m1 & below) < c1) ? 1 : 0);
            int kept = (k4 << 2) | (k2 << 1) | k1;
            float o = (float)kept * C;
            r[k] = __int_as_float(__float_as_int(o) | (__float_as_int(t[k]) & 0x80000000));
        }
    }

    stcs4(&ov[idx], w);                           // coalesced streaming store
}

extern "C" void kernel_launch(void* const* d_in, const int* in_sizes, int n_in,
                              void* d_out, int out_size) {
    const float* w     = (const float*)d_in[0];
    const float* alpha = (const float*)d_in[1];
    const int*   nt    = (const int*)d_in[2];
    int n = in_sizes[0];
    int nvec = n / 4;

    int na = (nvec + AT - 1) / AT;                // 32768 for 4096x8192
    if (na > MAXP) na = MAXP;

    reduceA<<<na, AT>>>((const float4*)w, nvec);

    // reduceBC with PDL: launches during reduceA's tail; waits for g_part visibility.
    {
        cudaLaunchAttribute attr[1];
        attr[0].id = cudaLaunchAttributeProgrammaticStreamSerialization;
        attr[0].val.programmaticStreamSerializationAllowed = 1;
        cudaLaunchConfig_t cfg = {};
        cfg.gridDim = dim3(1, 1, 1);
        cfg.blockDim = dim3(1024, 1, 1);
        cfg.attrs = attr;
        cfg.numAttrs = 1;
        cfg.stream = 0;
        cudaLaunchKernelEx(&cfg, reduceBC, alpha, na, (long long)n);
    }

    // quant with PDL: first wave launches during reduceBC, issues input LDGs pre-wait.
    {
        int qb = (nvec + QT - 1) / QT;
        cudaLaunchAttribute attr[1];
        attr[0].id = cudaLaunchAttributeProgrammaticStreamSerialization;
        attr[0].val.programmaticStreamSerializationAllowed = 1;
        cudaLaunchConfig_t cfg = {};
        cfg.gridDim = dim3(qb, 1, 1);
        cfg.blockDim = dim3(QT, 1, 1);
        cfg.attrs = attr;
        cfg.numAttrs = 1;
        cfg.stream = 0;
        cudaLaunchKernelEx(&cfg, quant, (const float4*)w, (float4*)d_out, nt, nvec);
    }
}

// round 12
// speedup vs baseline: 1.4147x; 1.4147x over previous
#include <cuda_runtime.h>
#include <cstdint>

// weight_quantize_fn: out = alpha * SF * q_kept * sign, with group-of-16 term budget.
// R11: single fused persistent kernel. Phase 1 = R2's measured-best reduce shape.
//      Grid-wide sync via counter + monotone epoch (graph-replay safe; 1184 CTAs
//      co-resident by __launch_bounds__(256,8), so spin cannot deadlock).
//      Phase 2 = quant reading the SAME addresses -> L2 hits (input ~resident in
//      126MB L2 after phase 1); DRAM traffic in phase 2 ~= output writes only.

#define NB 1184
#define RT 256

__device__ double g_psum[NB];
__device__ double g_psq[NB];
__device__ float  g_consts[4];       // [0]=1/(std*alpha), [1]=-mean/(std*alpha), [2]=SF*alpha
__device__ unsigned g_done;          // atomicInc wraps to 0 each launch
__device__ volatile unsigned g_epoch;  // monotone across launches

__device__ __forceinline__ void stcs4(float4* p, float4 v) {
    asm volatile("st.global.cs.v4.f32 [%0], {%1, %2, %3, %4};"
                 :: "l"(p), "f"(v.x), "f"(v.y), "f"(v.z), "f"(v.w) : "memory");
}

__global__ void __launch_bounds__(RT, 8) fused(const float4* __restrict__ x,
                                               float4* __restrict__ ov,
                                               const float* __restrict__ alpha_p,
                                               const int* __restrict__ ntp,
                                               int nvec, long long n) {
    int tid = threadIdx.x;
    __shared__ double ss[RT], sq[RT];
    __shared__ bool is_last;

    // Pre-arrival epoch. Read before this CTA's atomicInc -> guaranteed pre-bump.
    unsigned e0 = 0;
    if (tid == 0) e0 = g_epoch;

    // ---------------- phase 1: sum / sumsq (R2 shape: 2 chains, grid-stride) ----------------
    float s0 = 0.f, s1 = 0.f, q0 = 0.f, q1 = 0.f;
    int stride = gridDim.x * RT;
    int i0 = blockIdx.x * RT + tid;
    int i = i0;
    for (; i + stride < nvec; i += 2 * stride) {
        float4 a = x[i];
        float4 b = x[i + stride];
        s0 += (a.x + a.y) + (a.z + a.w);
        q0 += (a.x * a.x + a.y * a.y) + (a.z * a.z + a.w * a.w);
        s1 += (b.x + b.y) + (b.z + b.w);
        q1 += (b.x * b.x + b.y * b.y) + (b.z * b.z + b.w * b.w);
    }
    if (i < nvec) {
        float4 a = x[i];
        s0 += (a.x + a.y) + (a.z + a.w);
        q0 += (a.x * a.x + a.y * a.y) + (a.z * a.z + a.w * a.w);
    }
    ss[tid] = (double)s0 + (double)s1;
    sq[tid] = (double)q0 + (double)q1;
    __syncthreads();
    for (int o = RT >> 1; o > 0; o >>= 1) {
        if (tid < o) { ss[tid] += ss[tid + o]; sq[tid] += sq[tid + o]; }
        __syncthreads();
    }
    if (tid == 0) { g_psum[blockIdx.x] = ss[0]; g_psq[blockIdx.x] = sq[0]; }

    // ---------------- grid sync: counter + last-CTA finalize + epoch bump ----------------
    __threadfence();
    if (tid == 0) {
        unsigned c = atomicInc(&g_done, gridDim.x - 1);   // wraps to 0 for next launch
        is_last = (c == gridDim.x - 1);
    }
    __syncthreads();
    if (is_last) {
        __threadfence();                                  // see all partials
        double s = 0.0, q = 0.0;
        for (int k = tid; k < (int)gridDim.x; k += RT) { s += g_psum[k]; q += g_psq[k]; }
        ss[tid] = s; sq[tid] = q;
        __syncthreads();
        for (int o = RT >> 1; o > 0; o >>= 1) {
            if (tid < o) { ss[tid] += ss[tid + o]; sq[tid] += sq[tid + o]; }
            __syncthreads();
        }
        if (tid == 0) {
            double N = (double)n;
            double mean = ss[0] / N;
            double var  = (sq[0] - N * mean * mean) / (N - 1.0);   // unbiased (ddof=1)
            double stdv = sqrt(var);
            double alpha = (double)(*alpha_p);
            double inv = 1.0 / (stdv * alpha);
            g_consts[0] = (float)inv;
            g_consts[1] = (float)(-mean * inv);
            g_consts[2] = (float)((double)(1.0f / 7.0f) * alpha);  // SF (fp32 1/7) * alpha
            __threadfence();                                       // release consts
            g_epoch = e0 + 1u;                                     // volatile store: go signal
        }
    }
    if (tid == 0) {
        while (g_epoch == e0) { __nanosleep(64); }
        __threadfence();                                  // acquire consts
    }
    __syncthreads();                                      // BAR drains + orders for all threads

    // ---------------- phase 2: quantize the same addresses (L2-resident) ----------------
    float scale = g_consts[0], bias = g_consts[1], C = g_consts[2];
    int budget = __ldg(ntp) * 16;                         // num_terms * group_size
    const float MAGIC = 8388608.0f;                       // 2^23: RN add == round-half-even
    int thr = 2 * budget - 16;

    for (int j = i0; __any_sync(0xffffffffu, j < nvec); j += stride) {
        bool act = (j < nvec);                            // clusters never split (nvec%4==0)
        float4 v = act ? x[j] : make_float4(0.f, 0.f, 0.f, 0.f);

        float t0 = fmaf(v.x, scale, bias);
        float t1 = fmaf(v.y, scale, bias);
        float t2 = fmaf(v.z, scale, bias);
        float t3 = fmaf(v.w, scale, bias);
        float f0 = fmaf(fminf(fabsf(t0), 1.0f), 7.0f, MAGIC);   // f = 2^23 + q (RN half-even)
        float f1 = fmaf(fminf(fabsf(t1), 1.0f), 7.0f, MAGIC);
        float f2 = fmaf(fminf(fabsf(t2), 1.0f), 7.0f, MAGIC);
        float f3 = fmaf(fminf(fabsf(t3), 1.0f), 7.0f, MAGIC);

        // Low byte of int-bit sum == sum(q) over this thread's 4; shfl folds 4-lane cluster.
        int qs = __float_as_int(f0) + __float_as_int(f1) +
                 __float_as_int(f2) + __float_as_int(f3);
        qs += __shfl_xor_sync(0xffffffffu, qs, 1);
        qs += __shfl_xor_sync(0xffffffffu, qs, 2);

        float4 w;
        // popc(q) <= (q+1)/2 for q in [0,7] => sum(q) <= 2*budget-16 ==> all terms kept.
        if ((qs & 0xff) <= thr) {
            // Fast path: qk == q. (f - MAGIC) is exact.
            w.x = __int_as_float(__float_as_int((f0 - MAGIC) * C) | (__float_as_int(t0) & 0x80000000));
            w.y = __int_as_float(__float_as_int((f1 - MAGIC) * C) | (__float_as_int(t1) & 0x80000000));
            w.z = __int_as_float(__float_as_int((f2 - MAGIC) * C) | (__float_as_int(t2) & 0x80000000));
            w.w = __int_as_float(__float_as_int((f3 - MAGIC) * C) | (__float_as_int(t3) & 0x80000000));
        } else {
            // Exact path (rare): stable-descending-sort semantics over the 48 terms.
            int lane = tid & 31;
            unsigned cmask = 0xFu << (lane & ~3);
            int pos = (lane & 3) * 4;
            int m1 = 0, m2 = 0, m4 = 0;
            int qq[4] = { __float_as_int(f0) & 7, __float_as_int(f1) & 7,
                          __float_as_int(f2) & 7, __float_as_int(f3) & 7 };
#pragma unroll
            for (int k = 0; k < 4; k++) {
                m1 |= (qq[k] & 1) << (pos + k);
                m2 |= ((qq[k] >> 1) & 1) << (pos + k);
                m4 |= ((qq[k] >> 2) & 1) << (pos + k);
            }
            m1 |= __shfl_xor_sync(cmask, m1, 1);  m1 |= __shfl_xor_sync(cmask, m1, 2);
            m2 |= __shfl_xor_sync(cmask, m2, 1);  m2 |= __shfl_xor_sync(cmask, m2, 2);
            m4 |= __shfl_xor_sync(cmask, m4, 1);  m4 |= __shfl_xor_sync(cmask, m4, 2);
            int c4 = min(__popc(m4), budget);
            int rem = budget - c4;
            int c2 = min(__popc(m2), rem); rem -= c2;
            int c1 = min(__popc(m1), rem);
            if (c1 < 0) c1 = 0;
            float ts[4] = {t0, t1, t2, t3};
            float* r = &w.x;
#pragma unroll
            for (int k = 0; k < 4; k++) {
                int i16 = pos + k;
                int below = (1 << i16) - 1;
                int k4 = ((m4 >> i16) & 1) & ((__popc(m4 & below) < c4) ? 1 : 0);
                int k2 = ((m2 >> i16) & 1) & ((__popc(m2 & below) < c2) ? 1 : 0);
                int k1 = ((m1 >> i16) & 1) & ((__popc(m1 & below) < c1) ? 1 : 0);
                int kept = (k4 << 2) | (k2 << 1) | k1;
                float o = (float)kept * C;
                r[k] = __int_as_float(__float_as_int(o) | (__float_as_int(ts[k]) & 0x80000000));
            }
        }

        if (act) stcs4(&ov[j], w);   // streaming store: keep input resident in L2
    }
}

extern "C" void kernel_launch(void* const* d_in, const int* in_sizes, int n_in,
                              void* d_out, int out_size) {
    const float* w     = (const float*)d_in[0];
    const float* alpha = (const float*)d_in[1];
    const int*   nt    = (const int*)d_in[2];
    int n = in_sizes[0];
    int nvec = n / 4;

    fused<<<NB, RT>>>((const float4*)w, (float4*)d_out, alpha, nt, nvec, (long long)n);
}

// round 13
// speedup vs baseline: 1.5813x; 1.1178x over previous
#include <cuda_runtime.h>
#include <cstdint>

// weight_quantize_fn: out = alpha * SF * q_kept * sign, with group-of-16 term budget.
// R13: recombine measured-best pieces. reduce = R2/R6 grid-stride shape (33.4us,
//      fastest of 6 tested variants) + R4's in-kernel last-block finalize (1184
//      same-address atomics ~1us; only pathological at 8192+, per R5). quant
//      unchanged (39.5us wall). Two launches, one gap. Plain cached loads in
//      reduce keep the input tail L2-resident for reverse-order quant.

#define NB 1184
#define RT 256
#define QT 256

__device__ double g_psum[NB];
__device__ double g_psq[NB];
__device__ float  g_consts[4];   // [0]=1/(std*alpha), [1]=-mean/(std*alpha), [2]=SF*alpha
__device__ unsigned g_done;      // atomicInc wraps to 0 each launch (graph-replay safe)

typedef unsigned long long u64;

// ---- packed f32x2 helpers (Blackwell) ----
__device__ __forceinline__ u64 pk2(float lo, float hi) {
    u64 r; asm("mov.b64 %0, {%1, %2};" : "=l"(r) : "f"(lo), "f"(hi)); return r;
}
__device__ __forceinline__ void upk2(u64 v, float& lo, float& hi) {
    asm("mov.b64 {%0, %1}, %2;" : "=f"(lo), "=f"(hi) : "l"(v));
}
__device__ __forceinline__ u64 ffma2(u64 a, u64 b, u64 c) {
    u64 d; asm("fma.rn.f32x2 %0, %1, %2, %3;" : "=l"(d) : "l"(a), "l"(b), "l"(c)); return d;
}
__device__ __forceinline__ u64 fadd2(u64 a, u64 b) {
    u64 d; asm("add.rn.f32x2 %0, %1, %2;" : "=l"(d) : "l"(a), "l"(b)); return d;
}
__device__ __forceinline__ u64 fmul2(u64 a, u64 b) {
    u64 d; asm("mul.rn.f32x2 %0, %1, %2;" : "=l"(d) : "l"(a), "l"(b)); return d;
}
__device__ __forceinline__ void stcs4(float4* p, float4 v) {
    asm volatile("st.global.cs.v4.f32 [%0], {%1, %2, %3, %4};"
                 :: "l"(p), "f"(v.x), "f"(v.y), "f"(v.z), "f"(v.w) : "memory");
}

// ---- pass 1: grid-stride partial sums (R2 shape) + last-block finalize ----
__global__ void __launch_bounds__(RT) reduce1(const float4* __restrict__ x,
                                              const float* __restrict__ alpha_p,
                                              int nvec, long long n) {
    __shared__ double ss[RT], sq[RT];
    __shared__ bool is_last;
    float s0 = 0.f, s1 = 0.f, q0 = 0.f, q1 = 0.f;   // 2 independent chains
    int stride = gridDim.x * RT;
    int i = blockIdx.x * RT + threadIdx.x;
    for (; i + stride < nvec; i += 2 * stride) {
        float4 a = x[i];
        float4 b = x[i + stride];
        s0 += (a.x + a.y) + (a.z + a.w);
        q0 += (a.x * a.x + a.y * a.y) + (a.z * a.z + a.w * a.w);
        s1 += (b.x + b.y) + (b.z + b.w);
        q1 += (b.x * b.x + b.y * b.y) + (b.z * b.z + b.w * b.w);
    }
    if (i < nvec) {
        float4 a = x[i];
        s0 += (a.x + a.y) + (a.z + a.w);
        q0 += (a.x * a.x + a.y * a.y) + (a.z * a.z + a.w * a.w);
    }
    ss[threadIdx.x] = (double)s0 + (double)s1;
    sq[threadIdx.x] = (double)q0 + (double)q1;
    __syncthreads();
    for (int o = RT >> 1; o > 0; o >>= 1) {
        if (threadIdx.x < o) {
            ss[threadIdx.x] += ss[threadIdx.x + o];
            sq[threadIdx.x] += sq[threadIdx.x + o];
        }
        __syncthreads();
    }
    if (threadIdx.x == 0) { g_psum[blockIdx.x] = ss[0]; g_psq[blockIdx.x] = sq[0]; }

    // Last-block finalize (deterministic; 1184 atomics ~ 1us, fine at this grid).
    __threadfence();
    if (threadIdx.x == 0) {
        unsigned c = atomicInc(&g_done, gridDim.x - 1);   // wraps to 0 for next launch
        is_last = (c == gridDim.x - 1);
    }
    __syncthreads();
    if (is_last) {
        __threadfence();
        double s = 0.0, q = 0.0;
        for (int k = threadIdx.x; k < (int)gridDim.x; k += RT) { s += g_psum[k]; q += g_psq[k]; }
        ss[threadIdx.x] = s; sq[threadIdx.x] = q;
        __syncthreads();
        for (int o = RT >> 1; o > 0; o >>= 1) {
            if (threadIdx.x < o) {
                ss[threadIdx.x] += ss[threadIdx.x + o];
                sq[threadIdx.x] += sq[threadIdx.x + o];
            }
            __syncthreads();
        }
        if (threadIdx.x == 0) {
            double N = (double)n;
            double mean = ss[0] / N;
            double var  = (sq[0] - N * mean * mean) / (N - 1.0);   // unbiased (ddof=1)
            double stdv = sqrt(var);
            double alpha = (double)(*alpha_p);
            double inv = 1.0 / (stdv * alpha);
            g_consts[0] = (float)inv;
            g_consts[1] = (float)(-mean * inv);
            g_consts[2] = (float)((double)(1.0f / 7.0f) * alpha);  // SF (fp32 1/7) * alpha
        }
    }
}

// ---- pass 2: quantize. One float4 per thread; 4-lane clusters own one group of 16 ----
__global__ void __launch_bounds__(QT) quant(const float4* __restrict__ xv,
                                            float4* __restrict__ ov,
                                            const int* __restrict__ ntp, int nvec) {
    // Reverse block order: consume the L2-resident tail left by reduce1 first.
    int rb = gridDim.x - 1 - blockIdx.x;
    int idx = rb * blockDim.x + threadIdx.x;
    if (idx >= nvec) return;

    float scale = g_consts[0], bias = g_consts[1], C = g_consts[2];
    const float MAGIC = 8388608.0f;               // 2^23: RN add == round-half-even to int
    u64 s2 = pk2(scale, scale);
    u64 b2 = pk2(bias, bias);
    u64 seven2  = pk2(7.0f, 7.0f);
    u64 magic2  = pk2(MAGIC, MAGIC);
    u64 nmagic2 = pk2(-MAGIC, -MAGIC);
    u64 C2 = pk2(C, C);

    float4 v = xv[idx];                           // fully coalesced
    float X[4] = {v.x, v.y, v.z, v.w};

    float t[4], f[4];
#pragma unroll
    for (int p = 0; p < 2; p++) {
        u64 t2 = ffma2(pk2(X[2 * p], X[2 * p + 1]), s2, b2);    // t = x*scale + bias
        upk2(t2, t[2 * p], t[2 * p + 1]);
        float al = fminf(fabsf(t[2 * p]), 1.0f);                // |clip(t)| — FMNMX with |src|
        float ah = fminf(fabsf(t[2 * p + 1]), 1.0f);
        u64 f2 = ffma2(pk2(al, ah), seven2, magic2);            // f = 2^23 + q (round-half-even)
        upk2(f2, f[2 * p], f[2 * p + 1]);
    }

    // Group sum of q over the 16 elements owned by this 4-lane cluster.
    int qs = __float_as_int(f[0]) + __float_as_int(f[1]) +
             __float_as_int(f[2]) + __float_as_int(f[3]);
    qs += __shfl_xor_sync(0xffffffffu, qs, 1);
    qs += __shfl_xor_sync(0xffffffffu, qs, 2);

    int budget = __ldg(ntp) * 16;                 // num_terms * group_size

    float4 w;
    float* r = &w.x;
    // popc(q) <= (q+1)/2 for q in [0,7]  =>  sum(q) <= 2*budget-16 guarantees terms <= budget.
    if ((qs & 0xff) <= 2 * budget - 16) {
        // Fast path: every term kept -> qk == q.
#pragma unroll
        for (int p = 0; p < 2; p++) {
            u64 qf2 = fadd2(pk2(f[2 * p], f[2 * p + 1]), nmagic2);  // exact: qf = q as float
            u64 o2  = fmul2(qf2, C2);                               // |out| = q*SF*alpha
            float ol, oh; upk2(o2, ol, oh);
            r[2 * p]     = __int_as_float(__float_as_int(ol) | (__float_as_int(t[2 * p])     & 0x80000000));
            r[2 * p + 1] = __int_as_float(__float_as_int(oh) | (__float_as_int(t[2 * p + 1]) & 0x80000000));
        }
    } else {
        // Exact path (rare): stable-descending-sort semantics.
        int lane = threadIdx.x & 31;
        unsigned cmask = 0xFu << (lane & ~3);     // the 4 lanes of this cluster
        int pos = (lane & 3) * 4;                 // this lane's element offset in the group
        int m1 = 0, m2 = 0, m4 = 0;
#pragma unroll
        for (int k = 0; k < 4; k++) {
            int q = __float_as_int(f[k]) & 7;
            m1 |= (q & 1) << (pos + k);
            m2 |= ((q >> 1) & 1) << (pos + k);
            m4 |= ((q >> 2) & 1) << (pos + k);
        }
        m1 |= __shfl_xor_sync(cmask, m1, 1);  m1 |= __shfl_xor_sync(cmask, m1, 2);
        m2 |= __shfl_xor_sync(cmask, m2, 1);  m2 |= __shfl_xor_sync(cmask, m2, 2);
        m4 |= __shfl_xor_sync(cmask, m4, 1);  m4 |= __shfl_xor_sync(cmask, m4, 2);
        int c4 = min(__popc(m4), budget);
        int rem = budget - c4;
        int c2 = min(__popc(m2), rem); rem -= c2;
        int c1 = min(__popc(m1), rem);
        if (c1 < 0) c1 = 0;
#pragma unroll
        for (int k = 0; k < 4; k++) {
            int i16 = pos + k;
            int below = (1 << i16) - 1;
            int k4 = ((m4 >> i16) & 1) & ((__popc(m4 & below) < c4) ? 1 : 0);
            int k2 = ((m2 >> i16) & 1) & ((__popc(m2 & below) < c2) ? 1 : 0);
            int k1 = ((m1 >> i16) & 1) & ((__popc(m1 & below) < c1) ? 1 : 0);
            int kept = (k4 << 2) | (k2 << 1) | k1;
            float o = (float)kept * C;
            r[k] = __int_as_float(__float_as_int(o) | (__float_as_int(t[k]) & 0x80000000));
        }
    }

    stcs4(&ov[idx], w);                           // coalesced streaming store
}

extern "C" void kernel_launch(void* const* d_in, const int* in_sizes, int n_in,
                              void* d_out, int out_size) {
    const float* w     = (const float*)d_in[0];
    const float* alpha = (const float*)d_in[1];
    const int*   nt    = (const int*)d_in[2];
    int n = in_sizes[0];
    int nvec = n / 4;

    reduce1<<<NB, RT>>>((const float4*)w, alpha, nvec, (long long)n);
    int qb = (nvec + QT - 1) / QT;
    quant<<<qb, QT>>>((const float4*)w, (float4*)d_out, nt, nvec);
}

// round 17
// speedup vs baseline: 1.6708x; 1.0566x over previous
#include <cuda_runtime.h>
#include <cstdint>

// weight_quantize_fn: out = alpha * SF * q_kept * sign, with group-of-16 term budget.
// R14: reduce pass rebuilt on TMA (cp.async.bulk -> SMEM). Six LDG-based variants
//      all paced at ~4.1 TB/s read-only; B300 docs say the ~6300 B/cyc chip ceiling
//      is path-independent and TMA-reachable. 740 CTAs, 2x20KB double buffer,
//      depth-2 pipeline, mbarrier completion. Finalize tail + quant = R13 (75.8us).

#define NB 740                 // 5 CTAs/SM x 148
#define RT 256
#define CHUNK_V4 1280          // float4 per chunk = 20KB
#define CHUNK_BYTES (CHUNK_V4 * 16)
#define QT 256

__device__ double g_psum[NB];
__device__ double g_psq[NB];
__device__ float  g_consts[4];   // [0]=1/(std*alpha), [1]=-mean/(std*alpha), [2]=SF*alpha
__device__ unsigned g_done;      // atomicInc wraps to 0 each launch (graph-replay safe)

typedef unsigned long long u64;

// ---- packed f32x2 helpers (Blackwell) ----
__device__ __forceinline__ u64 pk2(float lo, float hi) {
    u64 r; asm("mov.b64 %0, {%1, %2};" : "=l"(r) : "f"(lo), "f"(hi)); return r;
}
__device__ __forceinline__ void upk2(u64 v, float& lo, float& hi) {
    asm("mov.b64 {%0, %1}, %2;" : "=f"(lo), "=f"(hi) : "l"(v));
}
__device__ __forceinline__ u64 ffma2(u64 a, u64 b, u64 c) {
    u64 d; asm("fma.rn.f32x2 %0, %1, %2, %3;" : "=l"(d) : "l"(a), "l"(b), "l"(c)); return d;
}
__device__ __forceinline__ u64 fadd2(u64 a, u64 b) {
    u64 d; asm("add.rn.f32x2 %0, %1, %2;" : "=l"(d) : "l"(a), "l"(b)); return d;
}
__device__ __forceinline__ u64 fmul2(u64 a, u64 b) {
    u64 d; asm("mul.rn.f32x2 %0, %1, %2;" : "=l"(d) : "l"(a), "l"(b)); return d;
}
__device__ __forceinline__ void stcs4(float4* p, float4 v) {
    asm volatile("st.global.cs.v4.f32 [%0], {%1, %2, %3, %4};"
                 :: "l"(p), "f"(v.x), "f"(v.y), "f"(v.z), "f"(v.w) : "memory");
}

// ---- TMA / mbarrier primitives ----
__device__ __forceinline__ uint32_t smem_u32(const void* p) {
    uint32_t a;
    asm("{ .reg .u64 t; cvta.to.shared.u64 t, %1; cvt.u32.u64 %0, t; }" : "=r"(a) : "l"(p));
    return a;
}
__device__ __forceinline__ void mbar_init(uint32_t mbar, uint32_t cnt) {
    asm volatile("mbarrier.init.shared.b64 [%0], %1;" :: "r"(mbar), "r"(cnt) : "memory");
}
__device__ __forceinline__ void mbar_expect_tx(uint32_t mbar, uint32_t bytes) {
    asm volatile("mbarrier.arrive.expect_tx.shared.b64 _, [%0], %1;"
                 :: "r"(mbar), "r"(bytes) : "memory");
}
__device__ __forceinline__ void bulk_g2s(uint32_t dst, const void* src, uint32_t bytes, uint32_t mbar) {
    asm volatile("cp.async.bulk.shared::cta.global.mbarrier::complete_tx::bytes [%0], [%1], %2, [%3];"
                 :: "r"(dst), "l"(src), "r"(bytes), "r"(mbar) : "memory");
}
__device__ __forceinline__ void mbar_wait(uint32_t mbar, uint32_t parity) {
    uint32_t done;
    asm volatile("{\n\t.reg .pred p;\n\t"
                 "mbarrier.try_wait.parity.acquire.cta.shared::cta.b64 p, [%1], %2;\n\t"
                 "selp.b32 %0, 1, 0, p;\n\t}"
                 : "=r"(done) : "r"(mbar), "r"(parity) : "memory");
    if (!done) {
        asm volatile("{\n\t.reg .pred P1;\n\t"
                     "WL_%=:\n\t"
                     "mbarrier.try_wait.parity.acquire.cta.shared::cta.b64 P1, [%0], %1, 0x989680;\n\t"
                     "@P1 bra.uni WD_%=;\n\t"
                     "bra.uni WL_%=;\n\t"
                     "WD_%=:\n\t}"
                     :: "r"(mbar), "r"(parity) : "memory");
    }
}
__device__ __forceinline__ void fence_proxy_async_cta() {
    asm volatile("fence.proxy.async.shared::cta;" ::: "memory");
}

// ---- pass 1: TMA-staged reduce + last-block finalize ----
__global__ void __launch_bounds__(RT) reduce1(const float4* __restrict__ x,
                                              const float* __restrict__ alpha_p,
                                              int nvec, long long n) {
    __shared__ alignas(128) float4 buf[2][CHUNK_V4];
    __shared__ alignas(8) unsigned long long mbar_s[2];
    __shared__ double ssw[RT / 32], sqw[RT / 32];
    __shared__ bool is_last;

    int tid = threadIdx.x;
    uint32_t mb0 = smem_u32(&mbar_s[0]);
    uint32_t mb1 = smem_u32(&mbar_s[1]);
    uint32_t bu0 = smem_u32(&buf[0][0]);
    uint32_t bu1 = smem_u32(&buf[1][0]);

    if (tid == 0) {
        mbar_init(mb0, 1);
        mbar_init(mb1, 1);
        fence_proxy_async_cta();
    }
    __syncthreads();

    int nfull = nvec / CHUNK_V4;                 // full 20KB chunks
    // chunks for this CTA: c_i = blockIdx.x + i*gridDim.x
    int m = 0;
    if ((int)blockIdx.x < nfull) m = (nfull - blockIdx.x + gridDim.x - 1) / gridDim.x;

    // Prologue: issue chunks 0 and 1.
    if (tid == 0) {
        if (m > 0) { mbar_expect_tx(mb0, CHUNK_BYTES);
                     bulk_g2s(bu0, x + (long long)blockIdx.x * CHUNK_V4, CHUNK_BYTES, mb0); }
        if (m > 1) { mbar_expect_tx(mb1, CHUNK_BYTES);
                     bulk_g2s(bu1, x + ((long long)blockIdx.x + gridDim.x) * CHUNK_V4, CHUNK_BYTES, mb1); }
    }

    float s0 = 0.f, s1 = 0.f, q0 = 0.f, q1 = 0.f;   // 2 chains (even/odd k)
    int ph0 = 0, ph1 = 0;

    for (int i = 0; i < m; i++) {
        int b = i & 1;
        if (b == 0) { mbar_wait(mb0, ph0); ph0 ^= 1; }
        else        { mbar_wait(mb1, ph1); ph1 ^= 1; }

        const float4* bp = &buf[b][0];
#pragma unroll
        for (int k = 0; k < CHUNK_V4 / RT; k++) {      // 5 float4 per thread
            float4 a = bp[tid + k * RT];
            if (k & 1) {
                s1 += (a.x + a.y) + (a.z + a.w);
                q1 += (a.x * a.x + a.y * a.y) + (a.z * a.z + a.w * a.w);
            } else {
                s0 += (a.x + a.y) + (a.z + a.w);
                q0 += (a.x * a.x + a.y * a.y) + (a.z * a.z + a.w * a.w);
            }
        }
        __syncthreads();                                // all threads done with buf[b]
        if (tid == 0 && i + 2 < m) {
            long long c = (long long)blockIdx.x + (long long)(i + 2) * gridDim.x;
            uint32_t mb = b == 0 ? mb0 : mb1;
            uint32_t bu = b == 0 ? bu0 : bu1;
            mbar_expect_tx(mb, CHUNK_BYTES);
            bulk_g2s(bu, x + c * CHUNK_V4, CHUNK_BYTES, mb);
        }
    }

    // Tail (nvec % CHUNK_V4): last CTA mops up with plain LDG.
    if ((int)blockIdx.x == (int)gridDim.x - 1) {
        for (int i = nfull * CHUNK_V4 + tid; i < nvec; i += RT) {
            float4 a = x[i];
            s0 += (a.x + a.y) + (a.z + a.w);
            q0 += (a.x * a.x + a.y * a.y) + (a.z * a.z + a.w * a.w);
        }
    }

    // Block reduction (warp shuffle in double).
    double s = (double)s0 + (double)s1;
    double q = (double)q0 + (double)q1;
#pragma unroll
    for (int o = 16; o > 0; o >>= 1) {
        s += __shfl_down_sync(0xffffffffu, s, o);
        q += __shfl_down_sync(0xffffffffu, q, o);
    }
    int wid = tid >> 5, lane = tid & 31;
    if (lane == 0) { ssw[wid] = s; sqw[wid] = q; }
    __syncthreads();
    if (tid == 0) {
        double ts = 0.0, tq = 0.0;
#pragma unroll
        for (int k = 0; k < RT / 32; k++) { ts += ssw[k]; tq += sqw[k]; }
        g_psum[blockIdx.x] = ts;
        g_psq[blockIdx.x] = tq;
    }

    // Last-block finalize (deterministic; ~740 same-address atomics ~ <1us).
    __threadfence();
    if (tid == 0) {
        unsigned c = atomicInc(&g_done, gridDim.x - 1);   // wraps to 0 for next launch
        is_last = (c == gridDim.x - 1);
    }
    __syncthreads();
    if (is_last) {
        __threadfence();
        double ts = 0.0, tq = 0.0;
        for (int k = tid; k < (int)gridDim.x; k += RT) { ts += g_psum[k]; tq += g_psq[k]; }
#pragma unroll
        for (int o = 16; o > 0; o >>= 1) {
            ts += __shfl_down_sync(0xffffffffu, ts, o);
            tq += __shfl_down_sync(0xffffffffu, tq, o);
        }
        if (lane == 0) { ssw[wid] = ts; sqw[wid] = tq; }
        __syncthreads();
        if (tid == 0) {
            double fs = 0.0, fq = 0.0;
#pragma unroll
            for (int k = 0; k < RT / 32; k++) { fs += ssw[k]; fq += sqw[k]; }
            double N = (double)n;
            double mean = fs / N;
            double var  = (fq - N * mean * mean) / (N - 1.0);   // unbiased (ddof=1)
            double stdv = sqrt(var);
            double alpha = (double)(*alpha_p);
            double inv = 1.0 / (stdv * alpha);
            g_consts[0] = (float)inv;
            g_consts[1] = (float)(-mean * inv);
            g_consts[2] = (float)((double)(1.0f / 7.0f) * alpha);  // SF (fp32 1/7) * alpha
        }
    }
}

// ---- pass 2: quantize. One float4 per thread; 4-lane clusters own one group of 16 ----
__global__ void __launch_bounds__(QT) quant(const float4* __restrict__ xv,
                                            float4* __restrict__ ov,
                                            const int* __restrict__ ntp, int nvec) {
    // Reverse block order: consume the L2-resident tail left by reduce1 first.
    int rb = gridDim.x - 1 - blockIdx.x;
    int idx = rb * blockDim.x + threadIdx.x;
    if (idx >= nvec) return;

    float scale = g_consts[0], bias = g_consts[1], C = g_consts[2];
    const float MAGIC = 8388608.0f;               // 2^23: RN add == round-half-even to int
    u64 s2 = pk2(scale, scale);
    u64 b2 = pk2(bias, bias);
    u64 seven2  = pk2(7.0f, 7.0f);
    u64 magic2  = pk2(MAGIC, MAGIC);
    u64 nmagic2 = pk2(-MAGIC, -MAGIC);
    u64 C2 = pk2(C, C);

    float4 v = xv[idx];                           // fully coalesced
    float X[4] = {v.x, v.y, v.z, v.w};

    float t[4], f[4];
#pragma unroll
    for (int p = 0; p < 2; p++) {
        u64 t2 = ffma2(pk2(X[2 * p], X[2 * p + 1]), s2, b2);    // t = x*scale + bias
        upk2(t2, t[2 * p], t[2 * p + 1]);
        float al = fminf(fabsf(t[2 * p]), 1.0f);                // |clip(t)| — FMNMX with |src|
        float ah = fminf(fabsf(t[2 * p + 1]), 1.0f);
        u64 f2 = ffma2(pk2(al, ah), seven2, magic2);            // f = 2^23 + q (round-half-even)
        upk2(f2, f[2 * p], f[2 * p + 1]);
    }

    // Group sum of q over the 16 elements owned by this 4-lane cluster.
    int qs = __float_as_int(f[0]) + __float_as_int(f[1]) +
             __float_as_int(f[2]) + __float_as_int(f[3]);
    qs += __shfl_xor_sync(0xffffffffu, qs, 1);
    qs += __shfl_xor_sync(0xffffffffu, qs, 2);

    int budget = __ldg(ntp) * 16;                 // num_terms * group_size

    float4 w;
    float* r = &w.x;
    // popc(q) <= (q+1)/2 for q in [0,7]  =>  sum(q) <= 2*budget-16 guarantees terms <= budget.
    if ((qs & 0xff) <= 2 * budget - 16) {
        // Fast path: every term kept -> qk == q.
#pragma unroll
        for (int p = 0; p < 2; p++) {
            u64 qf2 = fadd2(pk2(f[2 * p], f[2 * p + 1]), nmagic2);  // exact: qf = q as float
            u64 o2  = fmul2(qf2, C2);                               // |out| = q*SF*alpha
            float ol, oh; upk2(o2, ol, oh);
            r[2 * p]     = __int_as_float(__float_as_int(ol) | (__float_as_int(t[2 * p])     & 0x80000000));
            r[2 * p + 1] = __int_as_float(__float_as_int(oh) | (__float_as_int(t[2 * p + 1]) & 0x80000000));
        }
    } else {
        // Exact path (rare): stable-descending-sort semantics.
        int lane = threadIdx.x & 31;
        unsigned cmask = 0xFu << (lane & ~3);     // the 4 lanes of this cluster
        int pos = (lane & 3) * 4;                 // this lane's element offset in the group
        int m1 = 0, m2 = 0, m4 = 0;
#pragma unroll
        for (int k = 0; k < 4; k++) {
            int q = __float_as_int(f[k]) & 7;
            m1 |= (q & 1) << (pos + k);
            m2 |= ((q >> 1) & 1) << (pos + k);
            m4 |= ((q >> 2) & 1) << (pos + k);
        }
        m1 |= __shfl_xor_sync(cmask, m1, 1);  m1 |= __shfl_xor_sync(cmask, m1, 2);
        m2 |= __shfl_xor_sync(cmask, m2, 1);  m2 |= __shfl_xor_sync(cmask, m2, 2);
        m4 |= __shfl_xor_sync(cmask, m4, 1);  m4 |= __shfl_xor_sync(cmask, m4, 2);
        int c4 = min(__popc(m4), budget);
        int rem = budget - c4;
        int c2 = min(__popc(m2), rem); rem -= c2;
        int c1 = min(__popc(m1), rem);
        if (c1 < 0) c1 = 0;
#pragma unroll
        for (int k = 0; k < 4; k++) {
            int i16 = pos + k;
            int below = (1 << i16) - 1;
            int k4 = ((m4 >> i16) & 1) & ((__popc(m4 & below) < c4) ? 1 : 0);
            int k2 = ((m2 >> i16) & 1) & ((__popc(m2 & below) < c2) ? 1 : 0);
            int k1 = ((m1 >> i16) & 1) & ((__popc(m1 & below) < c1) ? 1 : 0);
            int kept = (k4 << 2) | (k2 << 1) | k1;
            float o = (float)kept * C;
            r[k] = __int_as_float(__float_as_int(o) | (__float_as_int(t[k]) & 0x80000000));
        }
    }

    stcs4(&ov[idx], w);                           // coalesced streaming store
}

extern "C" void kernel_launch(void* const* d_in, const int* in_sizes, int n_in,
                              void* d_out, int out_size) {
    const float* w     = (const float*)d_in[0];
    const float* alpha = (const float*)d_in[1];
    const int*   nt    = (const int*)d_in[2];
    int n = in_sizes[0];
    int nvec = n / 4;

    reduce1<<<NB, RT>>>((const float4*)w, alpha, nvec, (long long)n);
    int qb = (nvec + QT - 1) / QT;
    quant<<<qb, QT>>>((const float4*)w, (float4*)d_out, nt, nvec);
}